// round 17
// baseline (speedup 1.0000x reference)
#include <cuda_runtime.h>
#include <math_constants.h>

#define MAXQ    4096
#define MAXM    100000
#define MARGIN  0.0625f

// Grid over [-4,4]^3, cell 0.25. Clamped binning is 1-Lipschitz, so any mean
// within distance 0.25 of a query lies in the query cell's 27-neighborhood.
// Exact for arbitrary inputs (border cells clamp-extended to infinity in the
// pruning bound).
#define GS      32
#define NC      (GS * GS * GS)     // 32768
#define SCANBLK 16                 // 16 blocks x 256 thr x 8 cells

#define FP_SCALE 17179869184.0     // 2^34

// ---- static device scratch (zero-init at load; invariants restored each run) ----
__device__ int                g_cnt[NC];        // re-zeroed by scan_kernel
__device__ int                g_off[NC + 1];
__device__ int                g_fill[NC];
__device__ float4             g_pts[MAXM];
__device__ unsigned long long g_state[SCANBLK]; // lookback: flag<<62 | value
__device__ unsigned long long g_acc;            // fixed-point loss accumulator
__device__ unsigned int       g_done;           // query ticket

__device__ __forceinline__ int cell1d(float v) {
    int c = (int)floorf((v + 4.0f) * 4.0f);
    return min(max(c, 0), GS - 1);
}
__device__ __forceinline__ int cidx(float x, float y, float z) {
    return (cell1d(z) * GS + cell1d(y)) * GS + cell1d(x);
}

// Per-axis distance from v to cell i's effective region (clamp-extended at borders)
__device__ __forceinline__ float axd(float v, int i) {
    float lo = fmaf(0.25f, (float)i, -4.0f);
    float hi = lo + 0.25f;
    float d = 0.f;
    if (i > 0 && v < lo)           d = lo - v;
    else if (i < GS - 1 && v > hi) d = v - hi;
    return d;
}

// Warp-min of a non-negative float in ONE instruction (bits monotone for f>=0)
__device__ __forceinline__ float warp_min_pos(float f) {
    return __uint_as_float(__reduce_min_sync(0xFFFFFFFFu, __float_as_uint(f)));
}

// Uniform-k selector of prefetched row offsets held in lanes' v0..v3
__device__ __forceinline__ int rowv(int k, int r, int v0, int v1, int v2, int v3) {
    int x;
    switch (k) {
        case 0:  x = __shfl_sync(0xFFFFFFFFu, v0, r); break;
        case 1:  x = __shfl_sync(0xFFFFFFFFu, v1, r); break;
        case 2:  x = __shfl_sync(0xFFFFFFFFu, v2, r); break;
        default: x = __shfl_sync(0xFFFFFFFFu, v3, r); break;
    }
    return x;
}

// 2-way unrolled strided candidate scan with dual accumulators
__device__ __forceinline__ void scan_range(int s, int e, int lane,
                                           float4 qv, float& lb) {
    float lbA = lb, lbB = lb;
    int t = s + lane;
    for (; t + 32 < e; t += 64) {
        float4 m0 = g_pts[t];
        float4 m1 = g_pts[t + 32];
        float dx0 = qv.x - m0.x, dy0 = qv.y - m0.y, dz0 = qv.z - m0.z;
        float dx1 = qv.x - m1.x, dy1 = qv.y - m1.y, dz1 = qv.z - m1.z;
        lbA = fminf(lbA, fmaf(dx0, dx0, fmaf(dy0, dy0, dz0 * dz0)));
        lbB = fminf(lbB, fmaf(dx1, dx1, fmaf(dy1, dy1, dz1 * dz1)));
    }
    if (t < e) {
        float4 m = g_pts[t];
        float dx = qv.x - m.x, dy = qv.y - m.y, dz = qv.z - m.z;
        lbA = fminf(lbA, fmaf(dx, dx, fmaf(dy, dy, dz * dz)));
    }
    lb = fminf(lbA, lbB);
}

// ---------------------------------------------------------------------------
// Kernel 1: reset lookback state + count means per cell (4/thread, float4)
// ---------------------------------------------------------------------------
__global__ void count_kernel(const float* __restrict__ means, int M) {
    int gid = blockIdx.x * blockDim.x + threadIdx.x;

    if (gid < SCANBLK) g_state[gid] = 0ull;

    int m0 = gid * 4;
    if (m0 + 4 <= M) {
        const float4* p = (const float4*)means + (size_t)gid * 3;
        float4 a = p[0], b = p[1], c = p[2];
        atomicAdd(&g_cnt[cidx(a.x, a.y, a.z)], 1);
        atomicAdd(&g_cnt[cidx(a.w, b.x, b.y)], 1);
        atomicAdd(&g_cnt[cidx(b.z, b.w, c.x)], 1);
        atomicAdd(&g_cnt[cidx(c.y, c.z, c.w)], 1);
    } else if (m0 < M) {
        for (int m = m0; m < M; ++m)
            atomicAdd(&g_cnt[cidx(means[3*m], means[3*m+1], means[3*m+2])], 1);
    }
}

// ---------------------------------------------------------------------------
// Kernel 2: single-kernel ordered exclusive scan (decoupled lookback).
// 16 blocks x 256 threads x 8 cells/thread.
// ---------------------------------------------------------------------------
__global__ void __launch_bounds__(256) scan_kernel() {
    __shared__ int ws_incl[8];
    __shared__ int ws_excl[8];
    __shared__ int sh_prefix;

    const int tid  = threadIdx.x;
    const int bid  = blockIdx.x;
    const int lane = tid & 31;
    const int w    = tid >> 5;
    const int base = bid * 2048 + tid * 8;

    int4 va = *(const int4*)&g_cnt[base];
    int4 vb = *(const int4*)&g_cnt[base + 4];
    int s = va.x + va.y + va.z + va.w + vb.x + vb.y + vb.z + vb.w;

    int inc = s;
#pragma unroll
    for (int o = 1; o < 32; o <<= 1) {
        int t = __shfl_up_sync(0xFFFFFFFFu, inc, o);
        if (lane >= o) inc += t;
    }
    if (lane == 31) ws_incl[w] = inc;
    __syncthreads();
    if (tid < 8) {
        int e = 0;
#pragma unroll
        for (int k = 0; k < 8; ++k)
            if (k < tid) e += ws_incl[k];
        ws_excl[tid] = e;
    }
    __syncthreads();

    const int block_total = ws_excl[7] + ws_incl[7];
    const int excl = (inc - s) + ws_excl[w];

    if (tid == 0) {
        atomicExch(&g_state[bid], (1ull << 62) | (unsigned long long)block_total);
        unsigned long long prefix = 0;
        for (int i = bid - 1; i >= 0;) {
            unsigned long long st;
            do { st = atomicAdd(&g_state[i], 0ull); } while ((st >> 62) == 0ull);
            prefix += st & 0x3FFFFFFFFFFFFFFFull;
            if ((st >> 62) == 2ull) break;
            --i;
        }
        atomicExch(&g_state[bid],
                   (2ull << 62) | (unsigned long long)(prefix + block_total));
        sh_prefix = (int)prefix;
    }
    __syncthreads();

    int p = sh_prefix + excl;
    int o0 = p;
    int o1 = o0 + va.x;
    int o2 = o1 + va.y;
    int o3 = o2 + va.z;
    int o4 = o3 + va.w;
    int o5 = o4 + vb.x;
    int o6 = o5 + vb.y;
    int o7 = o6 + vb.z;
    int4 pa = make_int4(o0, o1, o2, o3);
    int4 pb = make_int4(o4, o5, o6, o7);
    *(int4*)&g_off[base]      = pa;
    *(int4*)&g_off[base + 4]  = pb;
    *(int4*)&g_fill[base]     = pa;
    *(int4*)&g_fill[base + 4] = pb;
    *(int4*)&g_cnt[base]      = make_int4(0, 0, 0, 0);   // restore zero-invariant
    *(int4*)&g_cnt[base + 4]  = make_int4(0, 0, 0, 0);

    if (bid == SCANBLK - 1 && tid == 255)
        g_off[NC] = o7 + vb.w;
}

// ---------------------------------------------------------------------------
// Kernel 3: scatter means into cell-sorted order (4 means/thread, float4 loads)
// ---------------------------------------------------------------------------
__global__ void scatter_kernel(const float* __restrict__ means, int M) {
    int gid = blockIdx.x * blockDim.x + threadIdx.x;
    int m0 = gid * 4;
    if (m0 + 4 <= M) {
        const float4* p = (const float4*)means + (size_t)gid * 3;
        float4 a = p[0], b = p[1], c = p[2];
        int p0 = atomicAdd(&g_fill[cidx(a.x, a.y, a.z)], 1);
        g_pts[p0] = make_float4(a.x, a.y, a.z, 0.f);
        int p1 = atomicAdd(&g_fill[cidx(a.w, b.x, b.y)], 1);
        g_pts[p1] = make_float4(a.w, b.x, b.y, 0.f);
        int p2 = atomicAdd(&g_fill[cidx(b.z, b.w, c.x)], 1);
        g_pts[p2] = make_float4(b.z, b.w, c.x, 0.f);
        int p3 = atomicAdd(&g_fill[cidx(c.y, c.z, c.w)], 1);
        g_pts[p3] = make_float4(c.y, c.z, c.w, 0.f);
    } else if (m0 < M) {
        for (int m = m0; m < M; ++m) {
            float x = means[3*m], y = means[3*m+1], z = means[3*m+2];
            int pos = atomicAdd(&g_fill[cidx(x, y, z)], 1);
            g_pts[pos] = make_float4(x, y, z, 0.f);
        }
    }
}

// ---------------------------------------------------------------------------
// Kernel 4: TWO warps per query (doubles resident parallelism; the kernel is
// stall-bound at low occupancy, so wall time ~ stall-sum / resident warps).
//   Each warp: transform (uniform) -> prefetch 9 row offsets (lanes 0-8) ->
//   scan home cell -> REDUX -> bound -> scan its half of the neighborhood
//   (warp 0: rows 0-3 + home-row-left; warp 1: rows 5-8 + home-row-right),
//   pruned vs bound. Combine via smem atomicMin on float bits (non-negative
//   floats order as uints). Fused deterministic fixed-point reduction.
// ---------------------------------------------------------------------------
__global__ void __launch_bounds__(256) query_kernel(
        const float* __restrict__ outputs,
        const float* __restrict__ c2ws,
        const float* __restrict__ scales,
        float* __restrict__ out, int N, int Q) {
    __shared__ unsigned sbest[4];
    const int tid   = threadIdx.x;
    const int lane  = tid & 31;
    const int warp  = tid >> 5;
    const int qloc  = warp >> 1;               // query slot within block (0..3)
    const int half  = warp & 1;                // which half of neighborhood
    const int qid   = blockIdx.x * 4 + qloc;

    if (tid < 4) sbest[tid] = __float_as_uint(MARGIN);
    __syncthreads();

    float bestw = MARGIN;
    if (qid < Q) {                             // warp-uniform
        // --- query transform (uniform across warp; broadcast loads) ---
        const int b = qid / N;
        const float s = scales[b];
        const float* o  = outputs + (size_t)qid * 3;
        const float* cm = c2ws + (size_t)b * 16;
        const float ox = o[0], oy = o[1], oz = o[2];
        float4 qv;
        qv.x = fmaf(s, fmaf(ox, cm[0], fmaf(oy, cm[1], oz * cm[2])),  cm[3]);
        qv.y = fmaf(s, fmaf(ox, cm[4], fmaf(oy, cm[5], oz * cm[6])),  cm[7]);
        qv.z = fmaf(s, fmaf(ox, cm[8], fmaf(oy, cm[9], oz * cm[10])), cm[11]);
        qv.w = 0.f;

        const int cx = cell1d(qv.x), cy = cell1d(qv.y), cz = cell1d(qv.z);
        const int x0 = max(cx - 1, 0), x1 = min(cx + 1, GS - 1);

        // --- parallel row prefetch: lane r in [0,9) owns row (dz,dy) ---
        float byz = CUDART_INF_F;
        int v0 = 0, v1 = 0, v2 = 0, v3 = 0;
        if (lane < 9) {
            const int zi = cz + (lane / 3) - 1;
            const int yi = cy + (lane % 3) - 1;
            if (zi >= 0 && zi < GS && yi >= 0 && yi < GS) {
                const float az = axd(qv.z, zi);
                const float ay = axd(qv.y, yi);
                byz = fmaf(ay, ay, az * az);
                const int row = (zi * GS + yi) * GS;
                v0 = g_off[row + x0];
                v1 = g_off[row + min(x0 + 1, x1 + 1)];
                v2 = g_off[row + min(x0 + 2, x1 + 1)];
                v3 = g_off[row + min(x0 + 3, x1 + 1)];
            }
        }

        const int kc = cx - x0;                // home cell slot within row

        // --- home cell (both warps; tiny duplicate, yields the prune bound) ---
        float lb = MARGIN;
        scan_range(rowv(kc, 4, v0, v1, v2, v3),
                   rowv(kc + 1, 4, v0, v1, v2, v3), lane, qv, lb);
        const float bound = warp_min_pos(lb);

        // --- this warp's half of the neighborhood, pruned vs bound ---
        float lb2 = bound;
        if (bound > 0.0f) {
            const float axm = (cx - 1 >= 0) ? axd(qv.x, cx - 1) : 0.f;
            const float axp = (cx + 1 < GS) ? axd(qv.x, cx + 1) : 0.f;
            const float axm2 = axm * axm;
            const float axp2 = axp * axp;

            const int rbase = half ? 5 : 0;    // rows 0-3 or 5-8
#pragma unroll
            for (int i = 0; i < 4; ++i) {
                const int r = rbase + i;
                const float byz_r = __shfl_sync(0xFFFFFFFFu, byz, r);
                if (byz_r >= bound) continue;  // warp-uniform prune

                int xlo = cx, xhi = cx;
                if (cx - 1 >= x0 && axm2 + byz_r < bound) xlo = cx - 1;
                if (cx + 1 <= x1 && axp2 + byz_r < bound) xhi = cx + 1;

                scan_range(rowv(xlo - x0,     r, v0, v1, v2, v3),
                           rowv(xhi - x0 + 1, r, v0, v1, v2, v3),
                           lane, qv, lb2);
            }

            // home-row x-neighbors (byz = 0): left -> warp 0, right -> warp 1
            if (half == 0) {
                if (cx - 1 >= x0 && axm2 < bound)
                    scan_range(rowv(kc - 1, 4, v0, v1, v2, v3),
                               rowv(kc,     4, v0, v1, v2, v3), lane, qv, lb2);
            } else {
                if (cx + 1 <= x1 && axp2 < bound)
                    scan_range(rowv(kc + 1, 4, v0, v1, v2, v3),
                               rowv(kc + 2, 4, v0, v1, v2, v3), lane, qv, lb2);
            }
        }
        bestw = warp_min_pos(lb2);
    }

    if (lane == 0) atomicMin(&sbest[qloc], __float_as_uint(bestw));
    __syncthreads();

    if (tid == 0) {
        double s = 0.0;
#pragma unroll
        for (int k = 0; k < 4; ++k)
            s += (double)(MARGIN - __uint_as_float(sbest[k]));
        unsigned long long fx = (unsigned long long)__double2ll_rn(s * FP_SCALE);
        atomicAdd(&g_acc, fx);
        __threadfence();
        if (atomicAdd(&g_done, 1u) == gridDim.x - 1) {
            unsigned long long tot = atomicExch(&g_acc, 0ull);
            atomicExch(&g_done, 0u);
            out[0] = (float)(((double)tot / FP_SCALE) / (double)Q);
        }
    }
}

extern "C" void kernel_launch(void* const* d_in, const int* in_sizes, int n_in,
                              void* d_out, int out_size) {
    const float* outputs = (const float*)d_in[0];  // (B, N, 3)
    const float* c2ws    = (const float*)d_in[1];  // (B, 4, 4)
    const float* scales  = (const float*)d_in[2];  // (B,)
    const float* means   = (const float*)d_in[3];  // (M, 3)

    int B = in_sizes[2];
    int Q = in_sizes[0] / 3;              // B*N
    int N = (B > 0) ? (Q / B) : 0;
    int M = in_sizes[3] / 3;
    if (Q > MAXQ) Q = MAXQ;
    if (M > MAXM) M = MAXM;

    int mthreads = (M + 3) / 4;           // 4 means per thread
    int nbm = (mthreads + 255) / 256;
    int nqb = (Q + 3) / 4;                // 4 queries per block (2 warps each)

    count_kernel  <<<nbm, 256>>>(means, M);
    scan_kernel   <<<SCANBLK, 256>>>();
    scatter_kernel<<<nbm, 256>>>(means, M);
    query_kernel  <<<nqb, 256>>>(outputs, c2ws, scales, (float*)d_out, N, Q);
}